// round 3
// baseline (speedup 1.0000x reference)
#include <cuda_runtime.h>
#include <math.h>

#define N_NODES 100000
#define N_EDGES 100000
#define NNZ_MAX 1600000
#define C 128

// ---- scratch (device globals; allocation-free per harness rules) -----------
__device__ __align__(16) float g_T[(size_t)N_NODES * C];  // scatter target (51.2MB)
__device__ float g_ns[N_NODES];                           // x0 @ a_tgt
__device__ int   g_rowptr[N_EDGES + 1];
__device__ int   g_node[NNZ_MAX];
__device__ int   g_edge[NNZ_MAX];
__device__ float g_val[NNZ_MAX];
__device__ int   g_is64;
__device__ int   g_rolemap[3];   // [0]=node buf idx, [1]=edge buf idx, [2]=values buf idx

// ---- detect dtype (int32 vs int64) and buffer roles on-device --------------
// values buffer: floats (ones -> word 0x3F800000, huge as uint).
// int64 index buffer: every odd 32-bit word is a zero high-half.
// edge_idx: sorted; node_idx: not sorted.
__global__ void detect_kernel(const unsigned* __restrict__ b0,
                              const unsigned* __restrict__ b1,
                              const unsigned* __restrict__ b2, int nnz) {
    __shared__ int s_float[3], s_oddzero[3], s_sorted[3], s_is64;
    __shared__ unsigned s_vals[3][64];
    int t = threadIdx.x;            // 192 threads: 64 per buffer
    int b = t >> 6, k = t & 63;
    const unsigned* bufs[3] = {b0, b1, b2};
    if (t < 3) { s_float[t] = 1; s_oddzero[t] = 1; s_sorted[t] = 1; }
    __syncthreads();

    const unsigned* p = bufs[b];
    // positions spread across the first nnz 32-bit words (safe in both layouts)
    unsigned q = (unsigned)(((long long)k * (nnz - 2)) / 63);
    unsigned w_even = p[q & ~1u];
    unsigned w_odd  = p[q | 1u];
    if (w_even <= 0x01000000u) atomicAnd(&s_float[b], 0);   // small word -> not float
    if (w_odd != 0u)           atomicAnd(&s_oddzero[b], 0); // nonzero odd word -> not int64
    __syncthreads();

    if (t == 0) {
        int is64 = 1;
        for (int i = 0; i < 3; ++i)
            if (!s_float[i] && !s_oddzero[i]) is64 = 0;  // an int buffer with nonzero odd words
        s_is64 = is64;
    }
    __syncthreads();

    // sorted test on element values
    if (!s_float[b]) {
        long long e = ((long long)k * (nnz - 1)) / 63;
        unsigned v = s_is64 ? p[2 * e] : p[e];
        s_vals[b][k] = v;
    }
    __syncthreads();
    if (!s_float[b] && k < 63) {
        if (s_vals[b][k] > s_vals[b][k + 1]) atomicAnd(&s_sorted[b], 0);
    }
    __syncthreads();

    if (t == 0) {
        int fb = -1, eb = -1, nb = -1;
        for (int i = 0; i < 3; ++i) if (s_float[i]) fb = i;
        for (int i = 0; i < 3; ++i) {
            if (i == fb) continue;
            if (s_sorted[i] && eb < 0) eb = i; else nb = i;
        }
        // fallbacks (shouldn't trigger): keep dict order
        if (fb < 0) fb = 2;
        if (eb < 0) eb = 1;
        if (nb < 0) nb = 0;
        g_rolemap[0] = nb; g_rolemap[1] = eb; g_rolemap[2] = fb;
        g_is64 = s_is64;
    }
}

// ---- normalize: indices -> clamped int32, values -> float ------------------
__global__ void convert_kernel(const void* b0, const void* b1, const void* b2, int nnz) {
    int i = blockIdx.x * blockDim.x + threadIdx.x;
    if (i >= nnz) return;
    const void* bufs[3] = {b0, b1, b2};
    const void* pn = bufs[g_rolemap[0]];
    const void* pe = bufs[g_rolemap[1]];
    const void* pv = bufs[g_rolemap[2]];
    int is64 = g_is64;
    int n = is64 ? (int)((const long long*)pn)[i] : ((const int*)pn)[i];
    int e = is64 ? (int)((const long long*)pe)[i] : ((const int*)pe)[i];
    g_node[i] = min(max(n, 0), N_NODES - 1);
    g_edge[i] = min(max(e, 0), N_EDGES - 1);
    g_val[i]  = ((const float*)pv)[i];
}

// ---------------------------------------------------------------- zero T ----
__global__ void zero_T_kernel() {
    size_t i = (size_t)blockIdx.x * blockDim.x + threadIdx.x;
    size_t n4 = (size_t)N_NODES * C / 4;
    if (i < n4) reinterpret_cast<float4*>(g_T)[i] = make_float4(0.f, 0.f, 0.f, 0.f);
}

// ------------------------------------------------- rowptr via binary search -
__global__ void build_rowptr_kernel(int nnz) {
    int t = blockIdx.x * blockDim.x + threadIdx.x;
    if (t > N_EDGES) return;
    int key = t, lo = 0, hi = nnz;
    while (lo < hi) {
        int mid = (lo + hi) >> 1;
        if (g_edge[mid] < key) lo = mid + 1; else hi = mid;
    }
    g_rowptr[t] = lo;
}

// ------------------------------------------------- node scores: x0 @ a_tgt --
__global__ void node_scores_kernel(const float* __restrict__ x0,
                                   const float* __restrict__ att) {
    int w = (blockIdx.x * blockDim.x + threadIdx.x) >> 5;
    int lane = threadIdx.x & 31;
    if (w >= N_NODES) return;
    float4 a = *reinterpret_cast<const float4*>(att + C + lane * 4);
    float4 x = *reinterpret_cast<const float4*>(x0 + (size_t)w * C + lane * 4);
    float p = x.x * a.x + x.y * a.y + x.z * a.z + x.w * a.w;
    #pragma unroll
    for (int o = 16; o; o >>= 1) p += __shfl_xor_sync(0xffffffffu, p, o);
    if (lane == 0) g_ns[w] = p;
}

// ---- fused: per-edge segment sum (m in registers) + edge score + scatter ---
__global__ void edge_fused_kernel(const float* __restrict__ x0,
                                  const float* __restrict__ att) {
    int w = (blockIdx.x * blockDim.x + threadIdx.x) >> 5;
    int lane = threadIdx.x & 31;
    if (w >= N_EDGES) return;
    int lo = g_rowptr[w];
    int hi = g_rowptr[w + 1];
    if (lo == hi) return;

    float4 acc = make_float4(0.f, 0.f, 0.f, 0.f);
    for (int i = lo; i < hi; ++i) {
        int n = g_node[i];                  // uniform across warp -> broadcast
        float v = g_val[i];
        float4 xv = *reinterpret_cast<const float4*>(x0 + (size_t)n * C + lane * 4);
        acc.x = fmaf(v, xv.x, acc.x);
        acc.y = fmaf(v, xv.y, acc.y);
        acc.z = fmaf(v, xv.z, acc.z);
        acc.w = fmaf(v, xv.w, acc.w);
    }

    float4 asrc = *reinterpret_cast<const float4*>(att + lane * 4);
    float es = acc.x * asrc.x + acc.y * asrc.y + acc.z * asrc.z + acc.w * asrc.w;
    #pragma unroll
    for (int o = 16; o; o >>= 1) es += __shfl_xor_sync(0xffffffffu, es, o);

    for (int i = lo; i < hi; ++i) {
        int n = g_node[i];
        float v = g_val[i];
        float s = es + g_ns[n];
        float sc = (s > 0.f ? s : (expf(s) - 1.f)) * v;
        float* dst = g_T + (size_t)n * C + lane * 4;
        asm volatile("red.global.add.v4.f32 [%0], {%1,%2,%3,%4};"
                     :: "l"(dst), "f"(sc * acc.x), "f"(sc * acc.y),
                        "f"(sc * acc.z), "f"(sc * acc.w)
                     : "memory");
    }
}

// ---------------------------------------------------- out = T @ W (fp32) ----
__global__ void gemm_TW_kernel(const float* __restrict__ Wt, float* __restrict__ out) {
    extern __shared__ float smem[];
    float* Ws = smem;           // [128][128]
    float* As = smem + C * C;   // [64][128]
    int tid = threadIdx.x;
    int tr = tid >> 5;
    int tc = tid & 31;
    int m0 = blockIdx.x * 64;

    const float4* Wg4 = reinterpret_cast<const float4*>(Wt);
    float4* Ws4 = reinterpret_cast<float4*>(Ws);
    #pragma unroll
    for (int j = 0; j < 16; ++j) Ws4[tid + j * 256] = Wg4[tid + j * 256];

    float4* As4 = reinterpret_cast<float4*>(As);
    const float4* Tg4 = reinterpret_cast<const float4*>(g_T);
    #pragma unroll
    for (int j = 0; j < 8; ++j) {
        int row = tr + j * 8;
        int grow = m0 + row;
        float4 v = (grow < N_NODES) ? Tg4[(size_t)grow * 32 + tc]
                                    : make_float4(0.f, 0.f, 0.f, 0.f);
        As4[row * 32 + tc] = v;
    }
    __syncthreads();

    float4 acc[8];
    #pragma unroll
    for (int r = 0; r < 8; ++r) acc[r] = make_float4(0.f, 0.f, 0.f, 0.f);

    #pragma unroll 4
    for (int k = 0; k < C; ++k) {
        float4 wv = *reinterpret_cast<const float4*>(Ws + k * C + tc * 4);
        #pragma unroll
        for (int r = 0; r < 8; ++r) {
            float a = As[(tr + r * 8) * C + k];
            acc[r].x = fmaf(a, wv.x, acc[r].x);
            acc[r].y = fmaf(a, wv.y, acc[r].y);
            acc[r].z = fmaf(a, wv.z, acc[r].z);
            acc[r].w = fmaf(a, wv.w, acc[r].w);
        }
    }

    float4* out4 = reinterpret_cast<float4*>(out);
    #pragma unroll
    for (int r = 0; r < 8; ++r) {
        int grow = m0 + tr + r * 8;
        if (grow < N_NODES) out4[(size_t)grow * 32 + tc] = acc[r];
    }
}

// -----------------------------------------------------------------------------
extern "C" void kernel_launch(void* const* d_in, const int* in_sizes, int n_in,
                              void* d_out, int out_size) {
    // Map by element count: x_0 12.8M, weight 16384, att 256, three NNZ buffers.
    const float* x0 = nullptr; const float* weight = nullptr; const float* att = nullptr;
    const void* big[3] = {nullptr, nullptr, nullptr};
    int nnz = 0, big_seen = 0;
    for (int i = 0; i < n_in; ++i) {
        int sz = in_sizes[i];
        if (sz == N_NODES * C)      x0 = (const float*)d_in[i];
        else if (sz == C * C)       weight = (const float*)d_in[i];
        else if (sz == 2 * C)       att = (const float*)d_in[i];
        else if (big_seen < 3)      { big[big_seen++] = d_in[i]; nnz = sz; }
    }
    float* out = (float*)d_out;

    detect_kernel<<<1, 192>>>((const unsigned*)big[0], (const unsigned*)big[1],
                              (const unsigned*)big[2], nnz);
    convert_kernel<<<(nnz + 255) / 256, 256>>>(big[0], big[1], big[2], nnz);
    zero_T_kernel<<<(N_NODES * C / 4 + 255) / 256, 256>>>();
    build_rowptr_kernel<<<(N_EDGES + 1 + 255) / 256, 256>>>(nnz);
    node_scores_kernel<<<(N_NODES * 32 + 255) / 256, 256>>>(x0, att);
    edge_fused_kernel<<<(N_EDGES * 32 + 255) / 256, 256>>>(x0, att);

    int smem_bytes = (C * C + 64 * C) * (int)sizeof(float);  // 96KB
    cudaFuncSetAttribute(gemm_TW_kernel,
                         cudaFuncAttributeMaxDynamicSharedMemorySize, smem_bytes);
    gemm_TW_kernel<<<(N_NODES + 63) / 64, 256, smem_bytes>>>(weight, out);
}

// round 5
// speedup vs baseline: 1.0529x; 1.0529x over previous
#include <cuda_runtime.h>
#include <cuda_bf16.h>
#include <math.h>
#include <stdint.h>

#define N_NODES 100000
#define N_EDGES 100000
#define NNZ_MAX 1600000
#define C 128

// ---- scratch (device globals; allocation-free per harness rules) -----------
__device__ __align__(16) float g_T[(size_t)N_NODES * C];  // scatter target (51.2MB)
__device__ float g_ns[N_NODES];                           // x0 @ a_tgt
__device__ int   g_rowptr[N_EDGES + 1];
__device__ int   g_node[NNZ_MAX];
__device__ float g_val[NNZ_MAX];
__device__ int   g_is64;
__device__ int   g_rolemap[3];
// W^T pair-packed bf16 hi/lo: g_Wh[n*64 + kp] = {W[2kp][n], W[2kp+1][n]}
__device__ __align__(16) unsigned g_Wh[C * C / 2];
__device__ __align__(16) unsigned g_Wl[C * C / 2];

// ---- detect dtype (int32 vs int64) and buffer roles on-device --------------
__global__ void detect_kernel(const unsigned* __restrict__ b0,
                              const unsigned* __restrict__ b1,
                              const unsigned* __restrict__ b2, int nnz) {
    __shared__ int s_float[3], s_oddzero[3], s_sorted[3], s_is64;
    __shared__ unsigned s_vals[3][64];
    int t = threadIdx.x;
    int b = t >> 6, k = t & 63;
    const unsigned* bufs[3] = {b0, b1, b2};
    if (t < 3) { s_float[t] = 1; s_oddzero[t] = 1; s_sorted[t] = 1; }
    __syncthreads();

    const unsigned* p = bufs[b];
    unsigned q = (unsigned)(((long long)k * (nnz - 2)) / 63);
    unsigned w_even = p[q & ~1u];
    unsigned w_odd  = p[q | 1u];
    if (w_even <= 0x01000000u) atomicAnd(&s_float[b], 0);
    if (w_odd != 0u)           atomicAnd(&s_oddzero[b], 0);
    __syncthreads();

    if (t == 0) {
        int is64 = 1;
        for (int i = 0; i < 3; ++i)
            if (!s_float[i] && !s_oddzero[i]) is64 = 0;
        s_is64 = is64;
    }
    __syncthreads();

    if (!s_float[b]) {
        long long e = ((long long)k * (nnz - 1)) / 63;
        s_vals[b][k] = s_is64 ? p[2 * e] : p[e];
    }
    __syncthreads();
    if (!s_float[b] && k < 63)
        if (s_vals[b][k] > s_vals[b][k + 1]) atomicAnd(&s_sorted[b], 0);
    __syncthreads();

    if (t == 0) {
        int fb = -1, eb = -1, nb = -1;
        for (int i = 0; i < 3; ++i) if (s_float[i]) fb = i;
        for (int i = 0; i < 3; ++i) {
            if (i == fb) continue;
            if (s_sorted[i] && eb < 0) eb = i; else nb = i;
        }
        if (fb < 0) fb = 2;
        if (eb < 0) eb = 1;
        if (nb < 0) nb = 0;
        g_rolemap[0] = nb; g_rolemap[1] = eb; g_rolemap[2] = fb;
        g_is64 = s_is64;
    }
}

// ---- normalize inputs AND build rowptr by boundary-fill ---------------------
__global__ void convert_kernel(const void* b0, const void* b1, const void* b2, int nnz) {
    int i = blockIdx.x * blockDim.x + threadIdx.x;
    if (i >= nnz) return;
    const void* bufs[3] = {b0, b1, b2};
    const void* pn = bufs[g_rolemap[0]];
    const void* pe = bufs[g_rolemap[1]];
    const void* pv = bufs[g_rolemap[2]];
    int is64 = g_is64;
    int n = is64 ? (int)((const long long*)pn)[i] : ((const int*)pn)[i];
    g_node[i] = min(max(n, 0), N_NODES - 1);
    g_val[i]  = ((const float*)pv)[i];

    int ec = is64 ? (int)((const long long*)pe)[i] : ((const int*)pe)[i];
    ec = min(max(ec, 0), N_EDGES - 1);
    int ep = -1;
    if (i > 0) {
        ep = is64 ? (int)((const long long*)pe)[i - 1] : ((const int*)pe)[i - 1];
        ep = min(max(ep, 0), N_EDGES - 1);
    }
    for (int t = ep + 1; t <= ec; ++t) g_rowptr[t] = i;      // lower_bound fill
    if (i == nnz - 1)
        for (int t = ec + 1; t <= N_EDGES; ++t) g_rowptr[t] = nnz;
}

// ---------------------------------------------------------------- zero T ----
__global__ void zero_T_kernel() {
    size_t i = (size_t)blockIdx.x * blockDim.x + threadIdx.x;
    size_t n4 = (size_t)N_NODES * C / 4;
    if (i < n4) reinterpret_cast<float4*>(g_T)[i] = make_float4(0.f, 0.f, 0.f, 0.f);
}

// ---- weight -> W^T pair-packed hi/lo bf16 -----------------------------------
__global__ void wprep_kernel(const float* __restrict__ w) {
    int idx = blockIdx.x * blockDim.x + threadIdx.x;   // 8192 pairs
    if (idx >= C * C / 2) return;
    int n = idx >> 6;
    int k0 = (idx & 63) * 2;
    float a = w[k0 * C + n], b = w[(k0 + 1) * C + n];  // {W[k0][n], W[k0+1][n]}
    __nv_bfloat16 ah = __float2bfloat16(a), bh = __float2bfloat16(b);
    __nv_bfloat16 al = __float2bfloat16(a - __bfloat162float(ah));
    __nv_bfloat16 bl = __float2bfloat16(b - __bfloat162float(bh));
    g_Wh[idx] = (unsigned)__bfloat16_as_ushort(ah) | ((unsigned)__bfloat16_as_ushort(bh) << 16);
    g_Wl[idx] = (unsigned)__bfloat16_as_ushort(al) | ((unsigned)__bfloat16_as_ushort(bl) << 16);
}

// ------------------------------------------------- node scores: x0 @ a_tgt --
__global__ void node_scores_kernel(const float* __restrict__ x0,
                                   const float* __restrict__ att) {
    int w = (blockIdx.x * blockDim.x + threadIdx.x) >> 5;
    int lane = threadIdx.x & 31;
    if (w >= N_NODES) return;
    float4 a = *reinterpret_cast<const float4*>(att + C + lane * 4);
    float4 x = *reinterpret_cast<const float4*>(x0 + (size_t)w * C + lane * 4);
    float p = x.x * a.x + x.y * a.y + x.z * a.z + x.w * a.w;
    #pragma unroll
    for (int o = 16; o; o >>= 1) p += __shfl_xor_sync(0xffffffffu, p, o);
    if (lane == 0) g_ns[w] = p;
}

// ---- fused: per-edge segment sum (m in registers) + edge score + scatter ---
__global__ void edge_fused_kernel(const float* __restrict__ x0,
                                  const float* __restrict__ att) {
    int w = (blockIdx.x * blockDim.x + threadIdx.x) >> 5;
    int lane = threadIdx.x & 31;
    if (w >= N_EDGES) return;
    int lo = g_rowptr[w];
    int hi = g_rowptr[w + 1];
    if (lo == hi) return;

    float4 acc = make_float4(0.f, 0.f, 0.f, 0.f);
    for (int i = lo; i < hi; ++i) {
        int n = g_node[i];
        float v = g_val[i];
        float4 xv = *reinterpret_cast<const float4*>(x0 + (size_t)n * C + lane * 4);
        acc.x = fmaf(v, xv.x, acc.x);
        acc.y = fmaf(v, xv.y, acc.y);
        acc.z = fmaf(v, xv.z, acc.z);
        acc.w = fmaf(v, xv.w, acc.w);
    }

    float4 asrc = *reinterpret_cast<const float4*>(att + lane * 4);
    float es = acc.x * asrc.x + acc.y * asrc.y + acc.z * asrc.z + acc.w * asrc.w;
    #pragma unroll
    for (int o = 16; o; o >>= 1) es += __shfl_xor_sync(0xffffffffu, es, o);

    for (int i = lo; i < hi; ++i) {
        int n = g_node[i];
        float v = g_val[i];
        float s = es + g_ns[n];
        float sc = (s > 0.f ? s : (expf(s) - 1.f)) * v;
        float* dst = g_T + (size_t)n * C + lane * 4;
        asm volatile("red.global.add.v4.f32 [%0], {%1,%2,%3,%4};"
                     :: "l"(dst), "f"(sc * acc.x), "f"(sc * acc.y),
                        "f"(sc * acc.z), "f"(sc * acc.w)
                     : "memory");
    }
}

// ============== out = T @ W via mma.sync bf16 3-split (base sm_103) ==========
__device__ __forceinline__ void mma_bf16(float* c, const unsigned* a, const unsigned* b) {
    asm volatile(
        "mma.sync.aligned.m16n8k16.row.col.f32.bf16.bf16.f32 "
        "{%0,%1,%2,%3}, {%4,%5,%6,%7}, {%8,%9}, {%0,%1,%2,%3};"
        : "+f"(c[0]), "+f"(c[1]), "+f"(c[2]), "+f"(c[3])
        : "r"(a[0]), "r"(a[1]), "r"(a[2]), "r"(a[3]), "r"(b[0]), "r"(b[1]));
}

#define STR 68   // pair-words per row in smem (64 + 4 pad: conflict-free frags)

__global__ void __launch_bounds__(256, 1) gemm_mma_kernel(float* __restrict__ out) {
    extern __shared__ unsigned sm[];
    unsigned* Ah = sm;                 // [128][STR]
    unsigned* Al = sm + 128 * STR;
    unsigned* Wh = sm + 2 * 128 * STR;
    unsigned* Wl = sm + 3 * 128 * STR;
    int tid = threadIdx.x, wid = tid >> 5, lane = tid & 31;
    int m0 = blockIdx.x * 128;

    // stage W hi/lo (pair-packed [n][64] in gmem -> padded smem)
    #pragma unroll
    for (int j = 0; j < 32; ++j) {
        int i = tid + j * 256;
        int n = i >> 6, kp = i & 63;
        Wh[n * STR + kp] = g_Wh[i];
        Wl[n * STR + kp] = g_Wl[i];
    }
    // stage A tile: fp32 rows of g_T -> hi/lo bf16 pairs
    for (int i = tid; i < C * C / 2; i += 256) {
        int r = i >> 6, kp = i & 63;
        int grow = m0 + r;
        float a = 0.f, b = 0.f;
        if (grow < N_NODES) {
            float2 v = *reinterpret_cast<const float2*>(g_T + (size_t)grow * C + kp * 2);
            a = v.x; b = v.y;
        }
        __nv_bfloat16 ah = __float2bfloat16(a), bh = __float2bfloat16(b);
        __nv_bfloat16 al = __float2bfloat16(a - __bfloat162float(ah));
        __nv_bfloat16 bl = __float2bfloat16(b - __bfloat162float(bh));
        Ah[r * STR + kp] = (unsigned)__bfloat16_as_ushort(ah) | ((unsigned)__bfloat16_as_ushort(bh) << 16);
        Al[r * STR + kp] = (unsigned)__bfloat16_as_ushort(al) | ((unsigned)__bfloat16_as_ushort(bl) << 16);
    }
    __syncthreads();

    int g = lane >> 2, t = lane & 3;
    int row = wid * 16 + g;            // this thread's A rows: row, row+8

    float c[16][4];
    #pragma unroll
    for (int nt = 0; nt < 16; ++nt)
        c[nt][0] = c[nt][1] = c[nt][2] = c[nt][3] = 0.f;

    #pragma unroll
    for (int k0 = 0; k0 < 8; ++k0) {   // K chunks of 16 (8 pairs)
        int kb = k0 * 8;
        unsigned ah[4], al[4];
        ah[0] = Ah[row * STR + kb + t];       ah[1] = Ah[(row + 8) * STR + kb + t];
        ah[2] = Ah[row * STR + kb + t + 4];   ah[3] = Ah[(row + 8) * STR + kb + t + 4];
        al[0] = Al[row * STR + kb + t];       al[1] = Al[(row + 8) * STR + kb + t];
        al[2] = Al[row * STR + kb + t + 4];   al[3] = Al[(row + 8) * STR + kb + t + 4];
        #pragma unroll
        for (int nt = 0; nt < 16; ++nt) {
            int n = nt * 8 + g;
            unsigned bh[2], bl[2];
            bh[0] = Wh[n * STR + kb + t]; bh[1] = Wh[n * STR + kb + t + 4];
            bl[0] = Wl[n * STR + kb + t]; bl[1] = Wl[n * STR + kb + t + 4];
            mma_bf16(c[nt], ah, bh);   // Th*Wh
            mma_bf16(c[nt], ah, bl);   // Th*Wl
            mma_bf16(c[nt], al, bh);   // Tl*Wh
        }
    }

    // epilogue: D[g][2t],D[g][2t+1],D[g+8][2t],D[g+8][2t+1] per ntile
    int grow0 = m0 + row, grow1 = grow0 + 8;
    #pragma unroll
    for (int nt = 0; nt < 16; ++nt) {
        int col = nt * 8 + 2 * t;
        if (grow0 < N_NODES)
            *reinterpret_cast<float2*>(out + (size_t)grow0 * C + col) = make_float2(c[nt][0], c[nt][1]);
        if (grow1 < N_NODES)
            *reinterpret_cast<float2*>(out + (size_t)grow1 * C + col) = make_float2(c[nt][2], c[nt][3]);
    }
}
#define GEMM_SMEM (4 * 128 * STR * 4)   // 139264 B

// -----------------------------------------------------------------------------
extern "C" void kernel_launch(void* const* d_in, const int* in_sizes, int n_in,
                              void* d_out, int out_size) {
    const float* x0 = nullptr; const float* weight = nullptr; const float* att = nullptr;
    const void* big[3] = {nullptr, nullptr, nullptr};
    int nnz = 0, big_seen = 0;
    for (int i = 0; i < n_in; ++i) {
        int sz = in_sizes[i];
        if (sz == N_NODES * C)      x0 = (const float*)d_in[i];
        else if (sz == C * C)       weight = (const float*)d_in[i];
        else if (sz == 2 * C)       att = (const float*)d_in[i];
        else if (big_seen < 3)      { big[big_seen++] = d_in[i]; nnz = sz; }
    }
    float* out = (float*)d_out;

    detect_kernel<<<1, 192>>>((const unsigned*)big[0], (const unsigned*)big[1],
                              (const unsigned*)big[2], nnz);
    convert_kernel<<<(nnz + 255) / 256, 256>>>(big[0], big[1], big[2], nnz);
    zero_T_kernel<<<(N_NODES * C / 4 + 255) / 256, 256>>>();
    wprep_kernel<<<(C * C / 2 + 255) / 256, 256>>>(weight);
    node_scores_kernel<<<(N_NODES * 32 + 255) / 256, 256>>>(x0, att);
    edge_fused_kernel<<<(N_EDGES * 32 + 255) / 256, 256>>>(x0, att);

    cudaFuncSetAttribute(gemm_mma_kernel,
                         cudaFuncAttributeMaxDynamicSharedMemorySize, GEMM_SMEM);
    gemm_mma_kernel<<<(N_NODES + 127) / 128, 256, GEMM_SMEM>>>(out);
}